// round 14
// baseline (speedup 1.0000x reference)
#include <cuda_runtime.h>

// ============================================================================
// QCNN 8-qubit circuit — exact algebraic reduction to a 3x3 bilinear form.
// Single fused kernel, 128 CTAs x 512 threads (best-measured shape), per-warp
// build, NO block barrier, ONE smem exchange round.
//
// Layer-3 folded into the measurement via Heisenberg picture (verified R12):
//   A3^H (Z(x)I) A3 = h (x) I,  h = [[cos b, -sin b e^{ia}],[...,-cos b]].
// Layer-1 column computed per-lane in registers (no exchange needed): lane
// (r,c) forms A1[k][c] for k=0..3 directly from the trig table, then
// B[r][c] = sum_k A2_eff[r][k] * A1[k][c] — a single smem store round gives
// every lane the B columns for S = Re(B^H (h(x)I) B).
//
// Math (verified R1-R13, rel_err ~1e-7):
//     z   = (1, cos x0, sin x0) · M · (1, cos x1, sin x1)^T,  M real 3x3
//     out = sigmoid(weight * z)      (weight folded into M)
// ============================================================================

#define NWARP 16   // warps per 512-thread block

template <bool EXACT>
__device__ __forceinline__ void qcnn_body(
    const float* __restrict__ x,
    const float* __restrict__ params,
    const float* __restrict__ weight,
    float* __restrict__ out,
    int n,
    float (*sTrig)[32],
    float (*sBre)[16], float (*sBim)[16])
{
    const unsigned FULL = 0xFFFFFFFFu;
    int tid  = threadIdx.x;
    int wid  = tid >> 5;
    int lane = tid & 31;
    int i = blockIdx.x * (NWARP * 32) + tid;

    // ---- Issue the batch-data load first; everything overlaps it ----------
    float2 xv;
    if (EXACT) {
        xv = *reinterpret_cast<const float2*>(x + (size_t)i * 8);
    } else {
        xv = make_float2(0.0f, 0.0f);
        if (i < n)
            xv = *reinterpret_cast<const float2*>(x + (size_t)i * 8);
    }
    float wgt = __ldg(weight);

    // ---- per-element trig, hoisted into the shadow of the build -----------
    float S0, C0, S1, C1;
    __sincosf(xv.x, &S0, &C0);
    __sincosf(xv.y, &S1, &C1);

    // ---- 15 build angles, one per lane ------------------------------------
    // l in {0,1}: both wires; l=2: wire 0 only (U31 dropped by Heisenberg).
    if (lane < 15) {
        int l = lane / 6, rem = lane - l * 6;   // l=2 -> rem in 0..2
        int q = rem / 3, combo = rem - q * 3;
        const float* p = params + l * 24 + q * 3;       // a,b,g contiguous
        float ang;
        if (combo == 0)      ang = 0.5f * p[1];              // b/2
        else if (combo == 1) ang = 0.5f * (p[0] + p[2]);     // (a+g)/2
        else                 ang = 0.5f * (p[0] - p[2]);     // (a-g)/2
        float s, c;
        __sincosf(ang, &s, &c);
        sTrig[wid][(l * 12) + q * 6 + combo * 2 + 0] = c;
        sTrig[wid][(l * 12) + q * 6 + combo * 2 + 1] = s;
    }
    __syncwarp();

    // Lane (r,c); CNOT folded into each layer via row remap s() = 0,1,3,2.
    int r = (lane >> 2) & 3, c = lane & 3;
    int sr = (r >= 2) ? (5 - r) : r;
    int q0 = sr >> 1, q1 = sr & 1;

    // ---- layer-1 column c of A1, in registers (no exchange) ---------------
    // A1[k][c] = U0_1[s(k)>>1][c>>1] * U1_1[s(k)&1][c&1], s(k)=0,1,3,2.
    // U rows: row0 = [( cb*cp, -cb*sp), (-sb*cm, -sb*sm)]
    //         row1 = [( sb*cm, -sb*sm), ( cb*cp,  cb*sp)]
    float A1r[4], A1i[4];
    {
        const float* T = &sTrig[wid][0];
        float cb0 = T[0],  sb0 = T[1],  cp0 = T[2],  sp0 = T[3];
        float cm0 = T[4],  sm0 = T[5];
        float cb1 = T[6],  sb1 = T[7],  cp1 = T[8],  sp1 = T[9];
        float cm1 = T[10], sm1 = T[11];
        int cbit1 = (c >> 1) & 1, cbit0 = c & 1;

        // U0_1[0][cbit1], U0_1[1][cbit1]
        float a0r = cbit1 ? -sb0*cm0 :  cb0*cp0;
        float a0i = cbit1 ? -sb0*sm0 : -cb0*sp0;
        float a1r = cbit1 ?  cb0*cp0 :  sb0*cm0;
        float a1i = cbit1 ?  cb0*sp0 : -sb0*sm0;
        // U1_1[0][cbit0], U1_1[1][cbit0]
        float b0r = cbit0 ? -sb1*cm1 :  cb1*cp1;
        float b0i = cbit0 ? -sb1*sm1 : -cb1*sp1;
        float b1r = cbit0 ?  cb1*cp1 :  sb1*cm1;
        float b1i = cbit0 ?  cb1*sp1 : -sb1*sm1;

        // k=0 -> s=0 -> (0,0); k=1 -> s=1 -> (0,1); k=2 -> s=3 -> (1,1); k=3 -> s=2 -> (1,0)
        A1r[0] = a0r*b0r - a0i*b0i;  A1i[0] = a0r*b0i + a0i*b0r;
        A1r[1] = a0r*b1r - a0i*b1i;  A1i[1] = a0r*b1i + a0i*b1r;
        A1r[2] = a1r*b1r - a1i*b1i;  A1i[2] = a1r*b1i + a1i*b1r;
        A1r[3] = a1r*b0r - a1i*b0i;  A1i[3] = a1r*b0i + a1i*b0r;
    }

    // ---- layer 2 row r of A2_eff, then B[r][c] = sum_k A2[r][k] A1[k][c] --
    float wre, wim;
    {
        const float* T = &sTrig[wid][12];
        float cb0 = T[0],  sb0 = T[1],  cp0 = T[2],  sp0 = T[3];
        float cm0 = T[4],  sm0 = T[5];
        float cb1 = T[6],  sb1 = T[7],  cp1 = T[8],  sp1 = T[9];
        float cm1 = T[10], sm1 = T[11];

        float a0r, a0i, a1r, a1i;     // U0_2[q0][0], U0_2[q0][1]
        if (q0 == 0) { a0r =  cb0*cp0; a0i = -cb0*sp0; a1r = -sb0*cm0; a1i = -sb0*sm0; }
        else         { a0r =  sb0*cm0; a0i = -sb0*sm0; a1r =  cb0*cp0; a1i =  cb0*sp0; }
        float b0r, b0i, b1r, b1i;     // U1_2[q1][0], U1_2[q1][1]
        if (q1 == 0) { b0r =  cb1*cp1; b0i = -cb1*sp1; b1r = -sb1*cm1; b1i = -sb1*sm1; }
        else         { b0r =  sb1*cm1; b0i = -sb1*sm1; b1r =  cb1*cp1; b1i =  cb1*sp1; }

        float Kre[4], Kim[4];         // A2_eff[r][k] = U0[q0][k>>1]*U1[q1][k&1]
        Kre[0] = a0r*b0r - a0i*b0i;  Kim[0] = a0r*b0i + a0i*b0r;
        Kre[1] = a0r*b1r - a0i*b1i;  Kim[1] = a0r*b1i + a0i*b1r;
        Kre[2] = a1r*b0r - a1i*b0i;  Kim[2] = a1r*b0i + a1i*b0r;
        Kre[3] = a1r*b1r - a1i*b1i;  Kim[3] = a1r*b1i + a1i*b1r;

        float ar = 0.0f, ai = 0.0f;
        #pragma unroll
        for (int k = 0; k < 4; k++) {
            ar = fmaf(Kre[k], A1r[k], fmaf(-Kim[k], A1i[k], ar));
            ai = fmaf(Kre[k], A1i[k], fmaf( Kim[k], A1r[k], ai));
        }
        wre = ar;  wim = ai;
    }

    // ---- the ONLY exchange: B to smem -------------------------------------
    if (lane < 16) { sBre[wid][lane] = wre; sBim[wid][lane] = wim; }
    __syncwarp();

    // ---- layer 3 as a 2x2 Hermitian h = U30^H Z U30 ------------------------
    float h00, h01r, h01i;
    {
        const float* T = &sTrig[wid][24];
        float cb = T[0], sb = T[1], cp = T[2], sp = T[3], cm = T[4], sm = T[5];
        float cosb = fmaf(cb, cb, -sb * sb);
        float sinb = 2.0f * sb * cb;
        float cosa = fmaf(cp, cm, -sp * sm);
        float sina = fmaf(sp, cm,  cp * sm);
        h00  = cosb;
        h01r = -sinb * cosa;
        h01i = -sinb * sina;
    }

    // ---- S[a][b] = Re( B_col_a^H (h (x) I) B_col_b ), a=r, b=c ------------
    float s_ab = 0.0f;
    {
        int a = r, b = c;
        #pragma unroll
        for (int i2 = 0; i2 < 2; i2++) {
            float BaLr = sBre[wid][i2 * 4 + a],       BaLi = sBim[wid][i2 * 4 + a];
            float BaHr = sBre[wid][(2 + i2) * 4 + a], BaHi = sBim[wid][(2 + i2) * 4 + a];
            float BbLr = sBre[wid][i2 * 4 + b],       BbLi = sBim[wid][i2 * 4 + b];
            float BbHr = sBre[wid][(2 + i2) * 4 + b], BbHi = sBim[wid][(2 + i2) * 4 + b];

            // v = h00*BbL + h01*BbH ; w = conj(h01)*BbL - h00*BbH
            float vr = fmaf(h00, BbLr, fmaf(h01r, BbHr, -h01i * BbHi));
            float vi = fmaf(h00, BbLi, fmaf(h01r, BbHi,  h01i * BbHr));
            float wr = fmaf(h01r, BbLr, fmaf( h01i, BbLi, -h00 * BbHr));
            float wi = fmaf(h01r, BbLi, fmaf(-h01i, BbLr, -h00 * BbHi));

            s_ab += fmaf(BaLr, vr, BaLi * vi) + fmaf(BaHr, wr, BaHi * wi);
        }
    }

    // ---- broadcast the 10 needed S entries; every lane folds M ------------
    float s00 = __shfl_sync(FULL, s_ab, 0);
    float s11 = __shfl_sync(FULL, s_ab, 5);
    float s22 = __shfl_sync(FULL, s_ab, 10);
    float s33 = __shfl_sync(FULL, s_ab, 15);
    float s01 = __shfl_sync(FULL, s_ab, 1);
    float s23 = __shfl_sync(FULL, s_ab, 11);
    float s02 = __shfl_sync(FULL, s_ab, 2);
    float s13 = __shfl_sync(FULL, s_ab, 7);
    float s03 = __shfl_sync(FULL, s_ab, 3);
    float s12 = __shfl_sync(FULL, s_ab, 6);

    float q4 = 0.25f * wgt, q2 = 0.5f * wgt;
    float m00 = q4 * (s00 + s11 + s22 + s33);
    float m01 = q4 * (s00 - s11 + s22 - s33);
    float m02 = q2 * (s01 + s23);
    float m10 = q4 * (s00 + s11 - s22 - s33);
    float m11 = q4 * (s00 - s11 - s22 + s33);
    float m12 = q2 * (s01 - s23);
    float m20 = q2 * (s02 + s13);
    float m21 = q2 * (s02 - s13);
    float m22 = q2 * (s03 + s12);

    if (!EXACT && i >= n) return;

    // z = (1,C0,S0) M (1,C1,S1)^T   (weight already folded into M)
    float t0 = fmaf(m02, S1, fmaf(m01, C1, m00));
    float t1 = fmaf(m12, S1, fmaf(m11, C1, m10));
    float t2 = fmaf(m22, S1, fmaf(m21, C1, m20));
    float z  = fmaf(S0, t2, fmaf(C0, t1, t0));

    out[i] = __fdividef(1.0f, 1.0f + __expf(-z));
}

__global__ void __launch_bounds__(NWARP * 32) qcnn_fused_exact(
    const float* __restrict__ x, const float* __restrict__ params,
    const float* __restrict__ weight, float* __restrict__ out, int n)
{
    __shared__ float sTrig[NWARP][32];
    __shared__ float sBre[NWARP][16], sBim[NWARP][16];
    qcnn_body<true>(x, params, weight, out, n, sTrig, sBre, sBim);
}

__global__ void __launch_bounds__(NWARP * 32) qcnn_fused_guarded(
    const float* __restrict__ x, const float* __restrict__ params,
    const float* __restrict__ weight, float* __restrict__ out, int n)
{
    __shared__ float sTrig[NWARP][32];
    __shared__ float sBre[NWARP][16], sBim[NWARP][16];
    qcnn_body<false>(x, params, weight, out, n, sTrig, sBre, sBim);
}

extern "C" void kernel_launch(void* const* d_in, const int* in_sizes, int n_in,
                              void* d_out, int out_size) {
    const float* x      = (const float*)d_in[0];   // (65536, 8) fp32
    const float* params = (const float*)d_in[1];   // (3, 8, 3) fp32
    const float* weight = (const float*)d_in[2];   // scalar fp32
    float* out = (float*)d_out;                    // (65536,) fp32

    int n = in_sizes[0] / 8;                       // 65536

    int threads = NWARP * 32;                      // 512
    if ((n & (threads - 1)) == 0) {
        qcnn_fused_exact<<<n / threads, threads>>>(x, params, weight, out, n);
    } else {
        qcnn_fused_guarded<<<(n + threads - 1) / threads, threads>>>(
            x, params, weight, out, n);
    }
}

// round 15
// speedup vs baseline: 1.0363x; 1.0363x over previous
#include <cuda_runtime.h>

// ============================================================================
// QCNN 8-qubit circuit — exact algebraic reduction to a 3x3 bilinear form.
// FINAL FORM (R14 structure, kernel dur at the measured floor ~4.99us):
// single fused kernel, 128 CTAs x 512 threads, per-warp build, NO block
// barrier, ONE smem exchange round, layer-3 folded via Heisenberg picture.
//
// Derivation chain (verified over 14 rounds, rel_err ~1.06e-7):
//  1. CNOTs couple only disjoint qubit pairs -> state is a 4-way tensor
//     product; <Z_0> depends only on the (0,1) 2-qubit subsystem.
//  2. Batch-independent params -> the 3-layer 2-qubit circuit is one fixed
//     4x4 complex unitary; real product input -> z = psi^T S psi.
//  3. Double-angle identities -> z = (1,cos x0,sin x0) M (1,cos x1,sin x1)^T,
//     M real 3x3, weight folded in.
//  4. Heisenberg fold: A3^H (Z(x)I) A3 = h (x) I with 2x2 Hermitian h
//     (U31 drops out); build reduces to B = A2*A1 and S = Re(B^H (h(x)I) B).
//  5. Layer-1 column in registers -> only ONE smem exchange on the chain.
// ============================================================================

#define NWARP 16   // warps per 512-thread block

template <bool EXACT>
__device__ __forceinline__ void qcnn_body(
    const float* __restrict__ x,
    const float* __restrict__ params,
    const float* __restrict__ weight,
    float* __restrict__ out,
    int n,
    float (*sTrig)[32],
    float (*sBre)[16], float (*sBim)[16])
{
    const unsigned FULL = 0xFFFFFFFFu;
    int tid  = threadIdx.x;
    int wid  = tid >> 5;
    int lane = tid & 31;
    int i = blockIdx.x * (NWARP * 32) + tid;

    // ---- Issue the batch-data load first; everything overlaps it ----------
    float2 xv;
    if (EXACT) {
        xv = *reinterpret_cast<const float2*>(x + (size_t)i * 8);
    } else {
        xv = make_float2(0.0f, 0.0f);
        if (i < n)
            xv = *reinterpret_cast<const float2*>(x + (size_t)i * 8);
    }
    float wgt = __ldg(weight);

    // ---- per-element trig, hoisted into the shadow of the build -----------
    float S0, C0, S1, C1;
    __sincosf(xv.x, &S0, &C0);
    __sincosf(xv.y, &S1, &C1);

    // ---- 15 build angles, one per lane ------------------------------------
    // l in {0,1}: both wires; l=2: wire 0 only (U31 dropped by Heisenberg).
    if (lane < 15) {
        int l = lane / 6, rem = lane - l * 6;   // l=2 -> rem in 0..2
        int q = rem / 3, combo = rem - q * 3;
        const float* p = params + l * 24 + q * 3;       // a,b,g contiguous
        float ang;
        if (combo == 0)      ang = 0.5f * p[1];              // b/2
        else if (combo == 1) ang = 0.5f * (p[0] + p[2]);     // (a+g)/2
        else                 ang = 0.5f * (p[0] - p[2]);     // (a-g)/2
        float s, c;
        __sincosf(ang, &s, &c);
        sTrig[wid][(l * 12) + q * 6 + combo * 2 + 0] = c;
        sTrig[wid][(l * 12) + q * 6 + combo * 2 + 1] = s;
    }
    __syncwarp();

    // Lane (r,c); CNOT folded into each layer via row remap s() = 0,1,3,2.
    int r = (lane >> 2) & 3, c = lane & 3;
    int sr = (r >= 2) ? (5 - r) : r;
    int q0 = sr >> 1, q1 = sr & 1;

    // ---- layer-1 column c of A1, in registers (no exchange) ---------------
    // A1[k][c] = U0_1[s(k)>>1][c>>1] * U1_1[s(k)&1][c&1], s(k)=0,1,3,2.
    // U rows: row0 = [( cb*cp, -cb*sp), (-sb*cm, -sb*sm)]
    //         row1 = [( sb*cm, -sb*sm), ( cb*cp,  cb*sp)]
    float A1r[4], A1i[4];
    {
        const float* T = &sTrig[wid][0];
        float cb0 = T[0],  sb0 = T[1],  cp0 = T[2],  sp0 = T[3];
        float cm0 = T[4],  sm0 = T[5];
        float cb1 = T[6],  sb1 = T[7],  cp1 = T[8],  sp1 = T[9];
        float cm1 = T[10], sm1 = T[11];
        int cbit1 = (c >> 1) & 1, cbit0 = c & 1;

        float a0r = cbit1 ? -sb0*cm0 :  cb0*cp0;
        float a0i = cbit1 ? -sb0*sm0 : -cb0*sp0;
        float a1r = cbit1 ?  cb0*cp0 :  sb0*cm0;
        float a1i = cbit1 ?  cb0*sp0 : -sb0*sm0;
        float b0r = cbit0 ? -sb1*cm1 :  cb1*cp1;
        float b0i = cbit0 ? -sb1*sm1 : -cb1*sp1;
        float b1r = cbit0 ?  cb1*cp1 :  sb1*cm1;
        float b1i = cbit0 ?  cb1*sp1 : -sb1*sm1;

        // k=0->s=0->(0,0); k=1->s=1->(0,1); k=2->s=3->(1,1); k=3->s=2->(1,0)
        A1r[0] = a0r*b0r - a0i*b0i;  A1i[0] = a0r*b0i + a0i*b0r;
        A1r[1] = a0r*b1r - a0i*b1i;  A1i[1] = a0r*b1i + a0i*b1r;
        A1r[2] = a1r*b1r - a1i*b1i;  A1i[2] = a1r*b1i + a1i*b1r;
        A1r[3] = a1r*b0r - a1i*b0i;  A1i[3] = a1r*b0i + a1i*b0r;
    }

    // ---- layer 2 row r of A2_eff, then B[r][c] = sum_k A2[r][k] A1[k][c] --
    float wre, wim;
    {
        const float* T = &sTrig[wid][12];
        float cb0 = T[0],  sb0 = T[1],  cp0 = T[2],  sp0 = T[3];
        float cm0 = T[4],  sm0 = T[5];
        float cb1 = T[6],  sb1 = T[7],  cp1 = T[8],  sp1 = T[9];
        float cm1 = T[10], sm1 = T[11];

        float a0r, a0i, a1r, a1i;     // U0_2[q0][0], U0_2[q0][1]
        if (q0 == 0) { a0r =  cb0*cp0; a0i = -cb0*sp0; a1r = -sb0*cm0; a1i = -sb0*sm0; }
        else         { a0r =  sb0*cm0; a0i = -sb0*sm0; a1r =  cb0*cp0; a1i =  cb0*sp0; }
        float b0r, b0i, b1r, b1i;     // U1_2[q1][0], U1_2[q1][1]
        if (q1 == 0) { b0r =  cb1*cp1; b0i = -cb1*sp1; b1r = -sb1*cm1; b1i = -sb1*sm1; }
        else         { b0r =  sb1*cm1; b0i = -sb1*sm1; b1r =  cb1*cp1; b1i =  cb1*sp1; }

        float Kre[4], Kim[4];         // A2_eff[r][k] = U0[q0][k>>1]*U1[q1][k&1]
        Kre[0] = a0r*b0r - a0i*b0i;  Kim[0] = a0r*b0i + a0i*b0r;
        Kre[1] = a0r*b1r - a0i*b1i;  Kim[1] = a0r*b1i + a0i*b1r;
        Kre[2] = a1r*b0r - a1i*b0i;  Kim[2] = a1r*b0i + a1i*b0r;
        Kre[3] = a1r*b1r - a1i*b1i;  Kim[3] = a1r*b1i + a1i*b1r;

        float ar = 0.0f, ai = 0.0f;
        #pragma unroll
        for (int k = 0; k < 4; k++) {
            ar = fmaf(Kre[k], A1r[k], fmaf(-Kim[k], A1i[k], ar));
            ai = fmaf(Kre[k], A1i[k], fmaf( Kim[k], A1r[k], ai));
        }
        wre = ar;  wim = ai;
    }

    // ---- the ONLY exchange: B to smem -------------------------------------
    if (lane < 16) { sBre[wid][lane] = wre; sBim[wid][lane] = wim; }
    __syncwarp();

    // ---- layer 3 as a 2x2 Hermitian h = U30^H Z U30 ------------------------
    float h00, h01r, h01i;
    {
        const float* T = &sTrig[wid][24];
        float cb = T[0], sb = T[1], cp = T[2], sp = T[3], cm = T[4], sm = T[5];
        float cosb = fmaf(cb, cb, -sb * sb);
        float sinb = 2.0f * sb * cb;
        float cosa = fmaf(cp, cm, -sp * sm);
        float sina = fmaf(sp, cm,  cp * sm);
        h00  = cosb;
        h01r = -sinb * cosa;
        h01i = -sinb * sina;
    }

    // ---- S[a][b] = Re( B_col_a^H (h (x) I) B_col_b ), a=r, b=c ------------
    float s_ab = 0.0f;
    {
        int a = r, b = c;
        #pragma unroll
        for (int i2 = 0; i2 < 2; i2++) {
            float BaLr = sBre[wid][i2 * 4 + a],       BaLi = sBim[wid][i2 * 4 + a];
            float BaHr = sBre[wid][(2 + i2) * 4 + a], BaHi = sBim[wid][(2 + i2) * 4 + a];
            float BbLr = sBre[wid][i2 * 4 + b],       BbLi = sBim[wid][i2 * 4 + b];
            float BbHr = sBre[wid][(2 + i2) * 4 + b], BbHi = sBim[wid][(2 + i2) * 4 + b];

            // v = h00*BbL + h01*BbH ; w = conj(h01)*BbL - h00*BbH
            float vr = fmaf(h00, BbLr, fmaf(h01r, BbHr, -h01i * BbHi));
            float vi = fmaf(h00, BbLi, fmaf(h01r, BbHi,  h01i * BbHr));
            float wr = fmaf(h01r, BbLr, fmaf( h01i, BbLi, -h00 * BbHr));
            float wi = fmaf(h01r, BbLi, fmaf(-h01i, BbLr, -h00 * BbHi));

            s_ab += fmaf(BaLr, vr, BaLi * vi) + fmaf(BaHr, wr, BaHi * wi);
        }
    }

    // ---- broadcast the 10 needed S entries; every lane folds M ------------
    float s00 = __shfl_sync(FULL, s_ab, 0);
    float s11 = __shfl_sync(FULL, s_ab, 5);
    float s22 = __shfl_sync(FULL, s_ab, 10);
    float s33 = __shfl_sync(FULL, s_ab, 15);
    float s01 = __shfl_sync(FULL, s_ab, 1);
    float s23 = __shfl_sync(FULL, s_ab, 11);
    float s02 = __shfl_sync(FULL, s_ab, 2);
    float s13 = __shfl_sync(FULL, s_ab, 7);
    float s03 = __shfl_sync(FULL, s_ab, 3);
    float s12 = __shfl_sync(FULL, s_ab, 6);

    float q4 = 0.25f * wgt, q2 = 0.5f * wgt;
    float m00 = q4 * (s00 + s11 + s22 + s33);
    float m01 = q4 * (s00 - s11 + s22 - s33);
    float m02 = q2 * (s01 + s23);
    float m10 = q4 * (s00 + s11 - s22 - s33);
    float m11 = q4 * (s00 - s11 - s22 + s33);
    float m12 = q2 * (s01 - s23);
    float m20 = q2 * (s02 + s13);
    float m21 = q2 * (s02 - s13);
    float m22 = q2 * (s03 + s12);

    if (!EXACT && i >= n) return;

    // z = (1,C0,S0) M (1,C1,S1)^T   (weight already folded into M)
    float t0 = fmaf(m02, S1, fmaf(m01, C1, m00));
    float t1 = fmaf(m12, S1, fmaf(m11, C1, m10));
    float t2 = fmaf(m22, S1, fmaf(m21, C1, m20));
    float z  = fmaf(S0, t2, fmaf(C0, t1, t0));

    out[i] = __fdividef(1.0f, 1.0f + __expf(-z));
}

__global__ void __launch_bounds__(NWARP * 32) qcnn_fused_exact(
    const float* __restrict__ x, const float* __restrict__ params,
    const float* __restrict__ weight, float* __restrict__ out, int n)
{
    __shared__ float sTrig[NWARP][32];
    __shared__ float sBre[NWARP][16], sBim[NWARP][16];
    qcnn_body<true>(x, params, weight, out, n, sTrig, sBre, sBim);
}

__global__ void __launch_bounds__(NWARP * 32) qcnn_fused_guarded(
    const float* __restrict__ x, const float* __restrict__ params,
    const float* __restrict__ weight, float* __restrict__ out, int n)
{
    __shared__ float sTrig[NWARP][32];
    __shared__ float sBre[NWARP][16], sBim[NWARP][16];
    qcnn_body<false>(x, params, weight, out, n, sTrig, sBre, sBim);
}

extern "C" void kernel_launch(void* const* d_in, const int* in_sizes, int n_in,
                              void* d_out, int out_size) {
    const float* x      = (const float*)d_in[0];   // (65536, 8) fp32
    const float* params = (const float*)d_in[1];   // (3, 8, 3) fp32
    const float* weight = (const float*)d_in[2];   // scalar fp32
    float* out = (float*)d_out;                    // (65536,) fp32

    int n = in_sizes[0] / 8;                       // 65536

    int threads = NWARP * 32;                      // 512
    if ((n & (threads - 1)) == 0) {
        qcnn_fused_exact<<<n / threads, threads>>>(x, params, weight, out, n);
    } else {
        qcnn_fused_guarded<<<(n + threads - 1) / threads, threads>>>(
            x, params, weight, out, n);
    }
}